// round 9
// baseline (speedup 1.0000x reference)
#include <cuda_runtime.h>
#include <math.h>

#define MAXN   65536
#define MAXL1  256
#define MAXV   256
#define MAXL2  16384
#define NB     148
#define NT     256

// ---------------- scratch ----------------
struct Scal {
    int bar[8];
    unsigned long long bestKey;
    int numL1, numV, numL2;
    int pad;
};
__device__ Scal  g_scal;                 // zeroed each call by memset node
__device__ int   g_counts[MAXN];         // self-cleaned (phase C)
__device__ int   g_flag[MAXN];           // self-cleaned (phase B)
__device__ float g_nodeMid[MAXV * 80];   // self-cleaned (phase D)
__device__ int   g_L1[MAXL1];
__device__ int   g_L2[MAXL2];
__device__ float g_w3j[675];

// path tables: TP2_PATHS = [(0,2),(1,1),(1,3),(2,0),(2,2),(3,1),(3,3)], l3=2
__device__ const int c_pl1[7]    = {0, 1, 1, 2, 2, 3, 3};
__device__ const int c_pl2[7]    = {2, 1, 3, 0, 2, 1, 3};
__device__ const int c_w3joff[7] = {0, 25, 70, 175, 200, 325, 430};
__device__ const int c_off[4]    = {0, 5, 20, 45};
__device__ const int c_shoff[4]  = {0, 1, 4, 9};

#define INV_SQRT20  0.2236067977499790f
#define INV_SQRT30  0.1825741858350554f
#define INV_SQRT6   0.4082482904638630f
#define NORM2MOM    1.679177f
#define ALPHA2      0.3779644730092272f
#define EMB_SCALE   8.4335731381317640f

// ---------------- grid barrier (persistent kernel, all CTAs resident) ----------
__device__ __forceinline__ void gbar(int id) {
    __syncthreads();
    if (threadIdx.x == 0) {
        __threadfence();                        // release
        atomicAdd(&g_scal.bar[id], 1);
        volatile int* p = (volatile int*)&g_scal.bar[id];
        while (*p < NB) { __nanosleep(32); }
        __threadfence();                        // acquire
    }
    __syncthreads();
}

// ---------------- Wigner 3j (double, on-device) ----------------
__device__ __forceinline__ double dfact(int n) {
    const double F[13] = {1., 1., 2., 6., 24., 120., 720., 5040., 40320.,
                          362880., 3628800., 39916800., 479001600.};
    return F[n];
}

__device__ double su2_cg(int j1, int m1, int j2, int m2, int j3, int m3) {
    if (m3 != m1 + m2) return 0.0;
    int vmin = max(max(-j1 + j2 + m3, -j1 + m1), 0);
    int vmax = min(min(j2 + j3 + m1, j3 - j1 + j2), j3 + m3);
    double C = sqrt((2.0 * j3 + 1.0) * dfact(j3 + j1 - j2) * dfact(j3 - j1 + j2) *
                    dfact(j1 + j2 - j3) * dfact(j3 + m3) * dfact(j3 - m3) /
                    (dfact(j1 + j2 + j3 + 1) * dfact(j1 - m1) * dfact(j1 + m1) *
                     dfact(j2 - m2) * dfact(j2 + m2)));
    double S = 0.0;
    for (int v = vmin; v <= vmax; v++) {
        double sgn = ((v + j2 + m2) & 1) ? -1.0 : 1.0;
        S += sgn / dfact(v) * dfact(j2 + j3 + m1 - v) * dfact(j1 - m1 + v) /
             dfact(j3 - j1 + j2 - v) / dfact(j3 + m3 - v) / dfact(v + j1 - j2 - m3);
    }
    return C * S;
}

__device__ void build_Q(int l, double2* Q) {
    for (int i = 0; i < 49; i++) Q[i] = make_double2(0.0, 0.0);
    const double inv = 0.70710678118654752440;
    for (int m = -l; m < 0; m++) {
        Q[(l + m) * 7 + (l - m)] = make_double2(inv, 0.0);
        Q[(l + m) * 7 + (l + m)] = make_double2(0.0, -inv);
    }
    Q[l * 7 + l] = make_double2(1.0, 0.0);
    for (int m = 1; m <= l; m++) {
        double sgn = (m & 1) ? -1.0 : 1.0;
        Q[(l + m) * 7 + (l + m)] = make_double2(sgn * inv, 0.0);
        Q[(l + m) * 7 + (l - m)] = make_double2(0.0, sgn * inv);
    }
    double pr, pi;
    switch (l & 3) {
        case 0: pr = 1;  pi = 0;  break;
        case 1: pr = 0;  pi = -1; break;
        case 2: pr = -1; pi = 0;  break;
        default: pr = 0; pi = 1;  break;
    }
    for (int i = 0; i < 49; i++) {
        double re = Q[i].x * pr - Q[i].y * pi;
        double im = Q[i].x * pi + Q[i].y * pr;
        Q[i] = make_double2(re, im);
    }
}

// all 7 paths, executed by one block (all 256 threads participate)
__device__ void w3j_block(int tid) {
    __shared__ double2 Q1[49], Q2[49], Q3[49];
    __shared__ double  C[245];
    __shared__ double  Cr[245];
    __shared__ double  red[NT / 32];
    __shared__ double  s_inorm;

    for (int p = 0; p < 7; p++) {
        int l1 = c_pl1[p], l2 = c_pl2[p];
        const int l3 = 2;
        int n1 = 2 * l1 + 1, n2 = 2 * l2 + 1;
        int tot = n1 * n2 * 5;

        if (tid == 0) { build_Q(l1, Q1); build_Q(l2, Q2); build_Q(2, Q3); }
        __syncthreads();
        for (int t = tid; t < tot; t += NT) {
            int i = t / (n2 * 5), r = t % (n2 * 5), k = r / 5, n = r % 5;
            int m1 = i - l1, m2 = k - l2;
            double v = 0.0;
            if (n == l3 + m1 + m2 && abs(m1 + m2) <= l3)
                v = su2_cg(l1, m1, l2, m2, l3, m1 + m2);
            C[t] = v;
        }
        __syncthreads();
        double part = 0.0;
        for (int t = tid; t < tot; t += NT) {
            int j = t / (n2 * 5), r = t % (n2 * 5), lc = r / 5, m = r % 5;
            double sre = 0.0;
            for (int i2 = 0; i2 < n1; i2++) {
                double2 qa = Q1[i2 * 7 + j];
                if (qa.x == 0.0 && qa.y == 0.0) continue;
                for (int k2 = 0; k2 < n2; k2++) {
                    int n = 2 + (i2 - l1) + (k2 - l2);
                    if (n < 0 || n > 4) continue;
                    double c = C[(i2 * n2 + k2) * 5 + n];
                    if (c == 0.0) continue;
                    double2 qb = Q2[k2 * 7 + lc];
                    double qr = qa.x * qb.x - qa.y * qb.y;
                    double qi = qa.x * qb.y + qa.y * qb.x;
                    double2 qg = Q3[n * 7 + m];
                    sre += c * (qr * qg.x + qi * qg.y);
                }
            }
            Cr[t] = sre;
            part += sre * sre;
        }
        // reduce sum of squares
        for (int o = 16; o > 0; o >>= 1)
            part += __shfl_down_sync(0xffffffffu, part, o);
        if ((tid & 31) == 0) red[tid >> 5] = part;
        __syncthreads();
        if (tid == 0) {
            double s = 0.0;
            for (int w = 0; w < NT / 32; w++) s += red[w];
            s_inorm = rsqrt(s);
        }
        __syncthreads();
        for (int t = tid; t < tot; t += NT)
            g_w3j[c_w3joff[p] + t] = (float)(Cr[t] * s_inorm);
        __syncthreads();
    }
}

// ---------------- per-edge math ----------------
__device__ __forceinline__ void sh16(float x, float y, float z, float* sh) {
    float x2 = x * x, y2 = y * y, z2 = z * z;
    sh[0]  = 1.0f;
    sh[1]  = 1.7320508075688772f * x;
    sh[2]  = 1.7320508075688772f * y;
    sh[3]  = 1.7320508075688772f * z;
    sh[4]  = 3.8729833462074170f * x * z;
    sh[5]  = 3.8729833462074170f * x * y;
    sh[6]  = 2.2360679774997896f * (y2 - 0.5f * (x2 + z2));
    sh[7]  = 3.8729833462074170f * y * z;
    sh[8]  = 0.5f * 3.8729833462074170f * (z2 - x2);
    sh[9]  = 2.0916500663351889f * x * (3.0f * z2 - x2);
    sh[10] = 10.246950765959598f * x * y * z;
    sh[11] = 1.6201851746019651f * x * (5.0f * y2 - 1.0f);
    sh[12] = 1.3228756555322954f * y * (5.0f * y2 - 3.0f);
    sh[13] = 1.6201851746019651f * z * (5.0f * y2 - 1.0f);
    sh[14] = 5.1234753829797990f * y * (z2 - x2);
    sh[15] = 2.0916500663351889f * z * (z2 - 3.0f * x2);
}

__device__ __forceinline__ float ufun(float t) {
    return (t > 0.0f) ? expf(-1.0f / t) : 0.0f;
}

__device__ __forceinline__ void pushCo(int e, const int* __restrict__ et) {
    int idx = atomicAdd(&g_scal.numL1, 1);
    if (idx < MAXL1) g_L1[idx] = e;
    int v = et[e];
    int old = atomicCAS(&g_flag[v], 0, INT_MIN);
    if (old == 0) {
        int s = atomicAdd(&g_scal.numV, 1);
        if (s < MAXV) atomicExch(&g_flag[v], s + 1);
    }
}

__device__ __forceinline__ void pushV(int e) {
    int idx = atomicAdd(&g_scal.numL2, 1);
    if (idx < MAXL2) g_L2[idx] = e;
}

// ---------------- the one persistent kernel ----------------
__global__ void __launch_bounds__(NT, 1)
k_all(const float* __restrict__ x, const float* __restrict__ pos,
      const int* __restrict__ ef, const int* __restrict__ et,
      const float* __restrict__ W1, const float* __restrict__ W2,
      const float* __restrict__ tp2, float* __restrict__ out,
      int N, int E) {
    const int tid = threadIdx.x, bid = blockIdx.x;
    const int g = bid * NT + tid;
    const int GS = NB * NT;
    const int EV = E >> 2;           // int4 vectors
    const int ER = EV << 2;          // remainder start

    // ===== Phase A: bincount (blocks 0..NB-2) | W3J (block NB-1) =====
    if (bid == NB - 1) {
        w3j_block(tid);
    } else {
        const int4* et4 = (const int4*)et;
        const int GA = (NB - 1) * NT;
        for (int t = bid * NT + tid; t < EV; t += GA) {
            int4 v = et4[t];
            atomicAdd(&g_counts[v.x], 1);
            atomicAdd(&g_counts[v.y], 1);
            atomicAdd(&g_counts[v.z], 1);
            atomicAdd(&g_counts[v.w], 1);
        }
        for (int e = ER + bid * NT + tid; e < E; e += GA)
            atomicAdd(&g_counts[et[e]], 1);
    }
    gbar(0);

    // ===== Phase B: argmax over counts (+ zero flags for phase C) =====
    {
        unsigned long long key = 0ull;
        for (int i = g; i < N; i += GS) {
            g_flag[i] = 0;
            unsigned long long k =
                ((unsigned long long)(unsigned)g_counts[i] << 32) |
                (unsigned long long)(0xFFFFFFFFu - (unsigned)i);
            if (k > key) key = k;
        }
        for (int o = 16; o > 0; o >>= 1) {
            unsigned long long other = __shfl_down_sync(0xffffffffu, key, o);
            if (other > key) key = other;
        }
        if ((tid & 31) == 0) atomicMax(&g_scal.bestKey, key);
    }
    gbar(1);

    // ===== Phase C: find Co's out-edges + target set V (+ zero counts) =====
    const int co = (int)(0xFFFFFFFFu - (unsigned)(g_scal.bestKey & 0xFFFFFFFFull));
    {
        for (int i = g; i < N; i += GS) g_counts[i] = 0;
        const int4* ef4 = (const int4*)ef;
        for (int t = g; t < EV; t += GS) {
            int4 v = ef4[t];
            if (v.x == co) pushCo(4 * t + 0, et);
            if (v.y == co) pushCo(4 * t + 1, et);
            if (v.z == co) pushCo(4 * t + 2, et);
            if (v.w == co) pushCo(4 * t + 3, et);
        }
        for (int e = ER + g; e < E; e += GS)
            if (ef[e] == co) pushCo(e, et);
    }
    gbar(2);

    // ===== Phase D: find out-edges of V (+ zero nodeMid) =====
    {
        for (int i = g; i < MAXV * 80; i += GS) g_nodeMid[i] = 0.0f;
        const int4* ef4 = (const int4*)ef;
        for (int t = g; t < EV; t += GS) {
            int4 v = ef4[t];
            if (g_flag[v.x] > 0) pushV(4 * t + 0);
            if (g_flag[v.y] > 0) pushV(4 * t + 1);
            if (g_flag[v.z] > 0) pushV(4 * t + 2);
            if (g_flag[v.w] > 0) pushV(4 * t + 3);
        }
        for (int e = ER + g; e < E; e += GS)
            if (g_flag[ef[e]] > 0) pushV(e);
    }
    gbar(3);

    // ===== Phase E: first tensor product + MLP on ~numL2 edges =====
    {
        int n = min(g_scal.numL2, MAXL2);
        for (int t = g; t < n; t += GS) {
            int e = g_L2[t];
            int a = ef[e], b = et[e];
            float dx = pos[3 * b + 0] - pos[3 * a + 0];
            float dy = pos[3 * b + 1] - pos[3 * a + 1];
            float dz = pos[3 * b + 2] - pos[3 * a + 2];
            float dist = sqrtf(dx * dx + dy * dy + dz * dz);
            float inv = 1.0f / dist;
            float sh[16];
            sh16(dx * inv, dy * inv, dz * inv, sh);

            float emb[20];
            float d6 = dist * 6.0f;
            #pragma unroll
            for (int i = 0; i < 20; i++) {
                float diff = d6 - (float)(i + 1);
                emb[i] = EMB_SCALE * ufun(diff + 1.0f) * ufun(1.0f - diff);
            }
            float h[30];
            #pragma unroll 5
            for (int j = 0; j < 30; j++) {
                float z = 0.0f;
                #pragma unroll
                for (int i = 0; i < 20; i++) z += emb[i] * W1[i * 30 + j];
                z *= INV_SQRT20;
                h[j] = NORM2MOM * z / (1.0f + expf(-z));
            }
            float tpw[20];
            #pragma unroll 5
            for (int k = 0; k < 20; k++) {
                float z = 0.0f;
                #pragma unroll
                for (int j = 0; j < 30; j++) z += h[j] * W2[j * 20 + k];
                tpw[k] = z * INV_SQRT30;
            }
            float s = x[b];
            int slot = g_flag[a] - 1;
            float* nm = g_nodeMid + slot * 80;
            #pragma unroll
            for (int u = 0; u < 5; u++)
                atomicAdd(&nm[u], s * tpw[u] * sh[0]);
            #pragma unroll
            for (int u = 0; u < 5; u++)
                for (int i = 0; i < 3; i++)
                    atomicAdd(&nm[5 + u * 3 + i], s * tpw[5 + u] * sh[1 + i]);
            #pragma unroll
            for (int u = 0; u < 5; u++)
                for (int i = 0; i < 5; i++)
                    atomicAdd(&nm[20 + u * 5 + i], s * tpw[10 + u] * sh[4 + i]);
            #pragma unroll
            for (int u = 0; u < 5; u++)
                for (int i = 0; i < 7; i++)
                    atomicAdd(&nm[45 + u * 7 + i], s * tpw[15 + u] * sh[9 + i]);
        }
    }
    gbar(4);

    // ===== Phase F: second tensor product over Co's edges (block 0 only) =====
    if (bid != 0) return;
    {
        __shared__ float acc[5];
        if (tid < 5) acc[tid] = 0.0f;
        __syncthreads();

        int n = min(g_scal.numL1, MAXL1);
        float o[5] = {0.f, 0.f, 0.f, 0.f, 0.f};
        for (int t = tid; t < n; t += NT) {
            int e = g_L1[t];
            int a = ef[e], b = et[e];
            float dx = pos[3 * b + 0] - pos[3 * a + 0];
            float dy = pos[3 * b + 1] - pos[3 * a + 1];
            float dz = pos[3 * b + 2] - pos[3 * a + 2];
            float inv = rsqrtf(dx * dx + dy * dy + dz * dz);
            float sh[16];
            sh16(dx * inv, dy * inv, dz * inv, sh);

            int slot = g_flag[b] - 1;
            float m[80];
            const float* nm = g_nodeMid + slot * 80;
            #pragma unroll
            for (int i = 0; i < 80; i++) m[i] = nm[i] * INV_SQRT6;

            for (int p = 0; p < 7; p++) {
                int l1 = c_pl1[p], l2 = c_pl2[p];
                int n1 = 2 * l1 + 1, n2 = 2 * l2 + 1;
                float av[7];
                for (int i = 0; i < n1; i++) {
                    float sacc = 0.0f;
                    for (int u = 0; u < 5; u++)
                        sacc += tp2[p * 5 + u] * m[c_off[l1] + u * n1 + i];
                    av[i] = sacc;
                }
                const float* W = g_w3j + c_w3joff[p];
                for (int i = 0; i < n1; i++)
                    for (int j = 0; j < n2; j++) {
                        float cij = av[i] * sh[c_shoff[l2] + j];
                        for (int k = 0; k < 5; k++)
                            o[k] += W[(i * n2 + j) * 5 + k] * cij;
                    }
            }
        }
        #pragma unroll
        for (int k = 0; k < 5; k++) atomicAdd(&acc[k], o[k] * ALPHA2);
        __syncthreads();
        if (tid < 5) out[tid] = acc[tid] * INV_SQRT6;
    }
}

// ---------------- launch ----------------
extern "C" void kernel_launch(void* const* d_in, const int* in_sizes, int n_in,
                              void* d_out, int out_size) {
    const float* x   = (const float*)d_in[0];
    const float* pos = (const float*)d_in[1];
    const int*   ef  = (const int*)d_in[2];
    const int*   et  = (const int*)d_in[3];
    const float* W1  = (const float*)d_in[4];
    const float* W2  = (const float*)d_in[5];
    const float* tp2 = (const float*)d_in[6];
    float* out = (float*)d_out;

    int N = in_sizes[0];
    int E = in_sizes[2];

    void* scal_ptr = nullptr;
    cudaGetSymbolAddress(&scal_ptr, g_scal);
    cudaMemsetAsync(scal_ptr, 0, sizeof(Scal), 0);

    k_all<<<NB, NT>>>(x, pos, ef, et, W1, W2, tp2, out, N, E);
}

// round 14
// speedup vs baseline: 2.8616x; 2.8616x over previous
#include <cuda_runtime.h>
#include <math.h>

#define MAXN   65536
#define MAXL1  256
#define MAXV   256
#define MAXL2  16384
#define NB     148
#define NW3J   7
#define NBC    (NB - NW3J)      // 141 bincount blocks
#define NT     256

// ---------------- scratch ----------------
struct Scal {
    int bar[8];
    unsigned long long bestKey;
    int numL1, numV, numL2;
    int pad;
};
__device__ Scal  g_scal;                 // zeroed each call by memset node
__device__ int   g_counts[MAXN];         // self-cleaned (phase C)
__device__ int   g_flag[MAXN];           // self-cleaned (phase B)
__device__ float g_nodeMid[MAXV * 80];   // self-cleaned (phase D)
__device__ int   g_L1[MAXL1];
__device__ int   g_L2[MAXL2];
__device__ float g_w3j[675];

// path tables: TP2_PATHS = [(0,2),(1,1),(1,3),(2,0),(2,2),(3,1),(3,3)], l3=2
__device__ const int c_pl1[7]    = {0, 1, 1, 2, 2, 3, 3};
__device__ const int c_pl2[7]    = {2, 1, 3, 0, 2, 1, 3};
__device__ const int c_w3joff[7] = {0, 25, 70, 175, 200, 325, 430};
__device__ const int c_off[4]    = {0, 5, 20, 45};
__device__ const int c_shoff[4]  = {0, 1, 4, 9};

#define INV_SQRT20  0.2236067977499790f
#define INV_SQRT30  0.1825741858350554f
#define INV_SQRT6   0.4082482904638630f
#define NORM2MOM    1.679177f
#define ALPHA2      0.3779644730092272f
#define EMB_SCALE   8.4335731381317640f

// ---------------- grid barrier (persistent kernel, all CTAs resident) ----------
__device__ __forceinline__ void gbar(int id) {
    __syncthreads();
    if (threadIdx.x == 0) {
        __threadfence();                        // release
        atomicAdd(&g_scal.bar[id], 1);
        volatile int* p = (volatile int*)&g_scal.bar[id];
        while (*p < NB) { __nanosleep(32); }
        __threadfence();                        // acquire
    }
    __syncthreads();
}

// ---------------- Wigner 3j (double, parallel, division-free) ----------------
__device__ __forceinline__ double dfact(int n) {
    const double F[13] = {1., 1., 2., 6., 24., 120., 720., 5040., 40320.,
                          362880., 3628800., 39916800., 479001600.};
    return F[n];
}
__device__ __forceinline__ double drfact(int n) {
    const double R[13] = {1.0, 1.0, 0.5, 1.0/6.0, 1.0/24.0, 1.0/120.0,
                          1.0/720.0, 1.0/5040.0, 1.0/40320.0, 1.0/362880.0,
                          1.0/3628800.0, 1.0/39916800.0, 1.0/479001600.0};
    return R[n];
}

// division-free CG coefficient (multiplies by reciprocal factorials)
__device__ double su2_cg(int j1, int m1, int j2, int m2, int j3, int m3) {
    if (m3 != m1 + m2) return 0.0;
    int vmin = max(max(-j1 + j2 + m3, -j1 + m1), 0);
    int vmax = min(min(j2 + j3 + m1, j3 - j1 + j2), j3 + m3);
    double C = sqrt((2.0 * j3 + 1.0) * dfact(j3 + j1 - j2) * dfact(j3 - j1 + j2) *
                    dfact(j1 + j2 - j3) * dfact(j3 + m3) * dfact(j3 - m3) *
                    drfact(j1 + j2 + j3 + 1) * drfact(j1 - m1) * drfact(j1 + m1) *
                    drfact(j2 - m2) * drfact(j2 + m2));
    double S = 0.0;
    for (int v = vmin; v <= vmax; v++) {
        double sgn = ((v + j2 + m2) & 1) ? -1.0 : 1.0;
        S += sgn * drfact(v) * dfact(j2 + j3 + m1 - v) * dfact(j1 - m1 + v) *
             drfact(j3 - j1 + j2 - v) * drfact(j3 + m3 - v) * drfact(v + j1 - j2 - m3);
    }
    return C * S;
}

// one entry (t in [0,49)) of the real-basis change matrix Q for degree l
__device__ __forceinline__ void fill_Q_entry(int l, double2* Q, int t) {
    int r = t / 7, c = t % 7;
    double re = 0.0, im = 0.0;
    const double inv = 0.70710678118654752440;
    int n = 2 * l + 1;
    if (r < n && c < n) {
        int m = r - l;
        if (m < 0) {
            if (c == l - m) re = inv;          // l + |m|
            else if (c == l + m) im = -inv;    // l - |m|
        } else if (m == 0) {
            if (c == l) re = 1.0;
        } else {
            double sgn = (m & 1) ? -1.0 : 1.0;
            if (c == l + m) re = sgn * inv;
            else if (c == l - m) im = sgn * inv;
        }
    }
    // multiply by (-i)^l
    double pr, pi;
    switch (l & 3) {
        case 0: pr = 1;  pi = 0;  break;
        case 1: pr = 0;  pi = -1; break;
        case 2: pr = -1; pi = 0;  break;
        default: pr = 0; pi = 1;  break;
    }
    Q[t] = make_double2(re * pr - im * pi, re * pi + im * pr);
}

// ONE path per block, fully parallel inside the block
__device__ void w3j_path(int p, int tid) {
    __shared__ double2 Q1[49], Q2[49], Q3[49];
    __shared__ double  C[245];
    __shared__ double  Cr[245];
    __shared__ double  red[NT / 32];
    __shared__ double  s_inorm;

    int l1 = c_pl1[p], l2 = c_pl2[p];
    const int l3 = 2;
    int n1 = 2 * l1 + 1, n2 = 2 * l2 + 1;
    int tot = n1 * n2 * 5;

    // parallel Q construction: 3 matrices in disjoint thread ranges
    if (tid < 49)                       fill_Q_entry(l1, Q1, tid);
    else if (tid >= 64 && tid < 113)    fill_Q_entry(l2, Q2, tid - 64);
    else if (tid >= 128 && tid < 177)   fill_Q_entry(2,  Q3, tid - 128);
    __syncthreads();

    // parallel complex CG tensor
    for (int t = tid; t < tot; t += NT) {
        int i = t / (n2 * 5), r = t % (n2 * 5), k = r / 5, n = r % 5;
        int m1 = i - l1, m2 = k - l2;
        double v = 0.0;
        if (n == l3 + m1 + m2 && abs(m1 + m2) <= l3)
            v = su2_cg(l1, m1, l2, m2, l3, m1 + m2);
        C[t] = v;
    }
    __syncthreads();

    // parallel basis-change einsum + sum of squares
    double part = 0.0;
    for (int t = tid; t < tot; t += NT) {
        int j = t / (n2 * 5), r = t % (n2 * 5), lc = r / 5, m = r % 5;
        double sre = 0.0;
        for (int i2 = 0; i2 < n1; i2++) {
            double2 qa = Q1[i2 * 7 + j];
            if (qa.x == 0.0 && qa.y == 0.0) continue;
            for (int k2 = 0; k2 < n2; k2++) {
                int n = 2 + (i2 - l1) + (k2 - l2);
                if (n < 0 || n > 4) continue;
                double c = C[(i2 * n2 + k2) * 5 + n];
                if (c == 0.0) continue;
                double2 qb = Q2[k2 * 7 + lc];
                double qr = qa.x * qb.x - qa.y * qb.y;
                double qi = qa.x * qb.y + qa.y * qb.x;
                double2 qg = Q3[n * 7 + m];
                sre += c * (qr * qg.x + qi * qg.y);
            }
        }
        Cr[t] = sre;
        part += sre * sre;
    }
    // parallel norm reduction
    for (int o = 16; o > 0; o >>= 1)
        part += __shfl_down_sync(0xffffffffu, part, o);
    if ((tid & 31) == 0) red[tid >> 5] = part;
    __syncthreads();
    if (tid == 0) {
        double s = 0.0;
        for (int w = 0; w < NT / 32; w++) s += red[w];
        s_inorm = rsqrt(s);
    }
    __syncthreads();
    for (int t = tid; t < tot; t += NT)
        g_w3j[c_w3joff[p] + t] = (float)(Cr[t] * s_inorm);
}

// ---------------- per-edge math ----------------
__device__ __forceinline__ void sh16(float x, float y, float z, float* sh) {
    float x2 = x * x, y2 = y * y, z2 = z * z;
    sh[0]  = 1.0f;
    sh[1]  = 1.7320508075688772f * x;
    sh[2]  = 1.7320508075688772f * y;
    sh[3]  = 1.7320508075688772f * z;
    sh[4]  = 3.8729833462074170f * x * z;
    sh[5]  = 3.8729833462074170f * x * y;
    sh[6]  = 2.2360679774997896f * (y2 - 0.5f * (x2 + z2));
    sh[7]  = 3.8729833462074170f * y * z;
    sh[8]  = 0.5f * 3.8729833462074170f * (z2 - x2);
    sh[9]  = 2.0916500663351889f * x * (3.0f * z2 - x2);
    sh[10] = 10.246950765959598f * x * y * z;
    sh[11] = 1.6201851746019651f * x * (5.0f * y2 - 1.0f);
    sh[12] = 1.3228756555322954f * y * (5.0f * y2 - 3.0f);
    sh[13] = 1.6201851746019651f * z * (5.0f * y2 - 1.0f);
    sh[14] = 5.1234753829797990f * y * (z2 - x2);
    sh[15] = 2.0916500663351889f * z * (z2 - 3.0f * x2);
}

__device__ __forceinline__ float ufun(float t) {
    return (t > 0.0f) ? expf(-1.0f / t) : 0.0f;
}

__device__ __forceinline__ void pushCo(int e, const int* __restrict__ et) {
    int idx = atomicAdd(&g_scal.numL1, 1);
    if (idx < MAXL1) g_L1[idx] = e;
    int v = et[e];
    int old = atomicCAS(&g_flag[v], 0, INT_MIN);
    if (old == 0) {
        int s = atomicAdd(&g_scal.numV, 1);
        if (s < MAXV) atomicExch(&g_flag[v], s + 1);
    }
}

__device__ __forceinline__ void pushV(int e) {
    int idx = atomicAdd(&g_scal.numL2, 1);
    if (idx < MAXL2) g_L2[idx] = e;
}

// ---------------- the one persistent kernel ----------------
__global__ void __launch_bounds__(NT, 1)
k_all(const float* __restrict__ x, const float* __restrict__ pos,
      const int* __restrict__ ef, const int* __restrict__ et,
      const float* __restrict__ W1, const float* __restrict__ W2,
      const float* __restrict__ tp2, float* __restrict__ out,
      int N, int E) {
    const int tid = threadIdx.x, bid = blockIdx.x;
    const int g = bid * NT + tid;
    const int GS = NB * NT;
    const int EV = E >> 2;           // int4 vectors
    const int ER = EV << 2;          // remainder start

    // ===== Phase A: bincount (blocks 0..NBC-1) | W3J (blocks NBC..NB-1, 1 path each) =====
    if (bid >= NBC) {
        w3j_path(bid - NBC, tid);
    } else {
        const int4* et4 = (const int4*)et;
        const int GA = NBC * NT;
        for (int t = bid * NT + tid; t < EV; t += GA) {
            int4 v = et4[t];
            atomicAdd(&g_counts[v.x], 1);
            atomicAdd(&g_counts[v.y], 1);
            atomicAdd(&g_counts[v.z], 1);
            atomicAdd(&g_counts[v.w], 1);
        }
        for (int e = ER + bid * NT + tid; e < E; e += GA)
            atomicAdd(&g_counts[et[e]], 1);
    }
    gbar(0);

    // ===== Phase B: argmax over counts (+ zero flags for phase C) =====
    {
        unsigned long long key = 0ull;
        for (int i = g; i < N; i += GS) {
            g_flag[i] = 0;
            unsigned long long k =
                ((unsigned long long)(unsigned)g_counts[i] << 32) |
                (unsigned long long)(0xFFFFFFFFu - (unsigned)i);
            if (k > key) key = k;
        }
        for (int o = 16; o > 0; o >>= 1) {
            unsigned long long other = __shfl_down_sync(0xffffffffu, key, o);
            if (other > key) key = other;
        }
        if ((tid & 31) == 0) atomicMax(&g_scal.bestKey, key);
    }
    gbar(1);

    // ===== Phase C: find Co's out-edges + target set V (+ zero counts) =====
    const int co = (int)(0xFFFFFFFFu - (unsigned)(g_scal.bestKey & 0xFFFFFFFFull));
    {
        for (int i = g; i < N; i += GS) g_counts[i] = 0;
        const int4* ef4 = (const int4*)ef;
        for (int t = g; t < EV; t += GS) {
            int4 v = ef4[t];
            if (v.x == co) pushCo(4 * t + 0, et);
            if (v.y == co) pushCo(4 * t + 1, et);
            if (v.z == co) pushCo(4 * t + 2, et);
            if (v.w == co) pushCo(4 * t + 3, et);
        }
        for (int e = ER + g; e < E; e += GS)
            if (ef[e] == co) pushCo(e, et);
    }
    gbar(2);

    // ===== Phase D: find out-edges of V (+ zero nodeMid) =====
    {
        for (int i = g; i < MAXV * 80; i += GS) g_nodeMid[i] = 0.0f;
        const int4* ef4 = (const int4*)ef;
        for (int t = g; t < EV; t += GS) {
            int4 v = ef4[t];
            if (g_flag[v.x] > 0) pushV(4 * t + 0);
            if (g_flag[v.y] > 0) pushV(4 * t + 1);
            if (g_flag[v.z] > 0) pushV(4 * t + 2);
            if (g_flag[v.w] > 0) pushV(4 * t + 3);
        }
        for (int e = ER + g; e < E; e += GS)
            if (g_flag[ef[e]] > 0) pushV(e);
    }
    gbar(3);

    // ===== Phase E: first tensor product + MLP on ~numL2 edges =====
    {
        int n = min(g_scal.numL2, MAXL2);
        for (int t = g; t < n; t += GS) {
            int e = g_L2[t];
            int a = ef[e], b = et[e];
            float dx = pos[3 * b + 0] - pos[3 * a + 0];
            float dy = pos[3 * b + 1] - pos[3 * a + 1];
            float dz = pos[3 * b + 2] - pos[3 * a + 2];
            float dist = sqrtf(dx * dx + dy * dy + dz * dz);
            float inv = 1.0f / dist;
            float sh[16];
            sh16(dx * inv, dy * inv, dz * inv, sh);

            float emb[20];
            float d6 = dist * 6.0f;
            #pragma unroll
            for (int i = 0; i < 20; i++) {
                float diff = d6 - (float)(i + 1);
                emb[i] = EMB_SCALE * ufun(diff + 1.0f) * ufun(1.0f - diff);
            }
            float h[30];
            #pragma unroll 5
            for (int j = 0; j < 30; j++) {
                float z = 0.0f;
                #pragma unroll
                for (int i = 0; i < 20; i++) z += emb[i] * W1[i * 30 + j];
                z *= INV_SQRT20;
                h[j] = NORM2MOM * z / (1.0f + expf(-z));
            }
            float tpw[20];
            #pragma unroll 5
            for (int k = 0; k < 20; k++) {
                float z = 0.0f;
                #pragma unroll
                for (int j = 0; j < 30; j++) z += h[j] * W2[j * 20 + k];
                tpw[k] = z * INV_SQRT30;
            }
            float s = x[b];
            int slot = g_flag[a] - 1;
            float* nm = g_nodeMid + slot * 80;
            #pragma unroll
            for (int u = 0; u < 5; u++)
                atomicAdd(&nm[u], s * tpw[u] * sh[0]);
            #pragma unroll
            for (int u = 0; u < 5; u++)
                for (int i = 0; i < 3; i++)
                    atomicAdd(&nm[5 + u * 3 + i], s * tpw[5 + u] * sh[1 + i]);
            #pragma unroll
            for (int u = 0; u < 5; u++)
                for (int i = 0; i < 5; i++)
                    atomicAdd(&nm[20 + u * 5 + i], s * tpw[10 + u] * sh[4 + i]);
            #pragma unroll
            for (int u = 0; u < 5; u++)
                for (int i = 0; i < 7; i++)
                    atomicAdd(&nm[45 + u * 7 + i], s * tpw[15 + u] * sh[9 + i]);
        }
    }
    gbar(4);

    // ===== Phase F: second tensor product over Co's edges (block 0 only) =====
    if (bid != 0) return;
    {
        __shared__ float acc[5];
        if (tid < 5) acc[tid] = 0.0f;
        __syncthreads();

        int n = min(g_scal.numL1, MAXL1);
        float o[5] = {0.f, 0.f, 0.f, 0.f, 0.f};
        for (int t = tid; t < n; t += NT) {
            int e = g_L1[t];
            int a = ef[e], b = et[e];
            float dx = pos[3 * b + 0] - pos[3 * a + 0];
            float dy = pos[3 * b + 1] - pos[3 * a + 1];
            float dz = pos[3 * b + 2] - pos[3 * a + 2];
            float inv = rsqrtf(dx * dx + dy * dy + dz * dz);
            float sh[16];
            sh16(dx * inv, dy * inv, dz * inv, sh);

            int slot = g_flag[b] - 1;
            float m[80];
            const float* nm = g_nodeMid + slot * 80;
            #pragma unroll
            for (int i = 0; i < 80; i++) m[i] = nm[i] * INV_SQRT6;

            for (int p = 0; p < 7; p++) {
                int l1 = c_pl1[p], l2 = c_pl2[p];
                int n1 = 2 * l1 + 1, n2 = 2 * l2 + 1;
                float av[7];
                for (int i = 0; i < n1; i++) {
                    float sacc = 0.0f;
                    for (int u = 0; u < 5; u++)
                        sacc += tp2[p * 5 + u] * m[c_off[l1] + u * n1 + i];
                    av[i] = sacc;
                }
                const float* W = g_w3j + c_w3joff[p];
                for (int i = 0; i < n1; i++)
                    for (int j = 0; j < n2; j++) {
                        float cij = av[i] * sh[c_shoff[l2] + j];
                        for (int k = 0; k < 5; k++)
                            o[k] += W[(i * n2 + j) * 5 + k] * cij;
                    }
            }
        }
        #pragma unroll
        for (int k = 0; k < 5; k++) atomicAdd(&acc[k], o[k] * ALPHA2);
        __syncthreads();
        if (tid < 5) out[tid] = acc[tid] * INV_SQRT6;
    }
}

// ---------------- launch ----------------
extern "C" void kernel_launch(void* const* d_in, const int* in_sizes, int n_in,
                              void* d_out, int out_size) {
    const float* x   = (const float*)d_in[0];
    const float* pos = (const float*)d_in[1];
    const int*   ef  = (const int*)d_in[2];
    const int*   et  = (const int*)d_in[3];
    const float* W1  = (const float*)d_in[4];
    const float* W2  = (const float*)d_in[5];
    const float* tp2 = (const float*)d_in[6];
    float* out = (float*)d_out;

    int N = in_sizes[0];
    int E = in_sizes[2];

    void* scal_ptr = nullptr;
    cudaGetSymbolAddress(&scal_ptr, g_scal);
    cudaMemsetAsync(scal_ptr, 0, sizeof(Scal), 0);

    k_all<<<NB, NT>>>(x, pos, ef, et, W1, W2, tp2, out, N, E);
}